// round 1
// baseline (speedup 1.0000x reference)
#include <cuda_runtime.h>
#include <cstdint>

// Problem constants
#define BATCH 4
#define SEQ 2048
#define DIN 1024
#define DOUT 1024
#define NHEAD 16
#define HDIM 64
#define MTOT (BATCH * SEQ)        // 8192

// ---------------- scratch (Q,K,V in [B,H,S,Dh] layout) ----------------
__device__ float g_q[BATCH * NHEAD * SEQ * HDIM];
__device__ float g_k[BATCH * NHEAD * SEQ * HDIM];
__device__ float g_v[BATCH * NHEAD * SEQ * HDIM];

// ---------------- fast exp2 (FMA-pipe only, avoids MUFU bottleneck) ----
__device__ __forceinline__ float fast_exp2(float x) {
    x = fmaxf(x, -120.0f);
    float r = x + 12582912.0f;            // round-to-nearest int (magic 1.5*2^23)
    float k = r - 12582912.0f;
    float f = x - k;                      // f in [-0.5, 0.5]
    int   ki = __float_as_int(r) - 0x4B400000;
    float p = 1.3333558e-3f;              // 2^f Taylor (ln2 powers), deg 5
    p = fmaf(p, f, 9.6181291e-3f);
    p = fmaf(p, f, 5.5504109e-2f);
    p = fmaf(p, f, 2.4022651e-1f);
    p = fmaf(p, f, 6.9314718e-1f);
    p = fmaf(p, f, 1.0f);
    return __int_as_float((ki + 127) << 23) * p;
}

// ---------------- QKV projection: [8192,1024] x [1024,1024] + bias -----
// BM=128, BN=128, BK=16, 256 threads, 8x8 micro-tile.
// gridDim = (8, 64, 3); z selects (Wq,bq)->g_q, (Wk,bk)->g_k, (Wv,bv)->g_v
#define PBM 128
#define PBN 128
#define PBK 16

__global__ __launch_bounds__(256, 2)
void proj_kernel(const float* __restrict__ x,
                 const float* __restrict__ Wq, const float* __restrict__ bq,
                 const float* __restrict__ Wk, const float* __restrict__ bk,
                 const float* __restrict__ Wv, const float* __restrict__ bv)
{
    const float* W;  const float* bias;  float* dst;
    if (blockIdx.z == 0)      { W = Wq; bias = bq; dst = g_q; }
    else if (blockIdx.z == 1) { W = Wk; bias = bk; dst = g_k; }
    else                      { W = Wv; bias = bv; dst = g_v; }

    __shared__ float As[PBK][PBM];   // A stored transposed
    __shared__ float Bs[PBK][PBN];

    const int tid = threadIdx.x;
    const int tx  = tid & 15;        // 16 col groups of 8
    const int ty  = tid >> 4;        // 16 row groups of 8
    const int m0  = blockIdx.y * PBM;
    const int n0  = blockIdx.x * PBN;

    float acc[8][8];
    #pragma unroll
    for (int i = 0; i < 8; i++)
        #pragma unroll
        for (int j = 0; j < 8; j++) acc[i][j] = 0.0f;

    for (int k0 = 0; k0 < DIN; k0 += PBK) {
        // load A tile 128x16 (transposed into As)
        #pragma unroll
        for (int it = 0; it < 2; it++) {
            int v   = tid + it * 256;     // 0..511 float4 slots
            int row = v >> 2;             // 4 float4 per row
            int c4  = v & 3;
            float4 a = *(const float4*)&x[(size_t)(m0 + row) * DIN + k0 + c4 * 4];
            As[c4 * 4 + 0][row] = a.x;
            As[c4 * 4 + 1][row] = a.y;
            As[c4 * 4 + 2][row] = a.z;
            As[c4 * 4 + 3][row] = a.w;
        }
        // load B tile 16x128
        #pragma unroll
        for (int it = 0; it < 2; it++) {
            int v   = tid + it * 256;
            int row = v >> 5;             // 32 float4 per row
            int c4  = v & 31;
            *(float4*)&Bs[row][c4 * 4] =
                *(const float4*)&W[(size_t)(k0 + row) * DOUT + n0 + c4 * 4];
        }
        __syncthreads();

        #pragma unroll
        for (int kk = 0; kk < PBK; kk++) {
            float a[8], b[8];
            *(float4*)&a[0] = *(float4*)&As[kk][ty * 8];
            *(float4*)&a[4] = *(float4*)&As[kk][ty * 8 + 4];
            *(float4*)&b[0] = *(float4*)&Bs[kk][tx * 8];
            *(float4*)&b[4] = *(float4*)&Bs[kk][tx * 8 + 4];
            #pragma unroll
            for (int i = 0; i < 8; i++)
                #pragma unroll
                for (int j = 0; j < 8; j++)
                    acc[i][j] = fmaf(a[i], b[j], acc[i][j]);
        }
        __syncthreads();
    }

    // bias + store into [B,H,S,Dh] layout
    float bb[8];
    *(float4*)&bb[0] = *(const float4*)&bias[n0 + tx * 8];
    *(float4*)&bb[4] = *(const float4*)&bias[n0 + tx * 8 + 4];

    const int bbatch = m0 >> 11;                  // 128 | 2048 -> one batch per block
    const int n_base = n0 + tx * 8;
    const int h      = n_base >> 6;               // 8-aligned inside a 64-wide head
    const int dbase  = n_base & 63;
    float* drow = dst + (size_t)(bbatch * NHEAD + h) * SEQ * HDIM;

    #pragma unroll
    for (int i = 0; i < 8; i++) {
        int s = (m0 & (SEQ - 1)) + ty * 8 + i;
        float4 o0 = make_float4(acc[i][0] + bb[0], acc[i][1] + bb[1],
                                acc[i][2] + bb[2], acc[i][3] + bb[3]);
        float4 o1 = make_float4(acc[i][4] + bb[4], acc[i][5] + bb[5],
                                acc[i][6] + bb[6], acc[i][7] + bb[7]);
        *(float4*)&drow[(size_t)s * HDIM + dbase]     = o0;
        *(float4*)&drow[(size_t)s * HDIM + dbase + 4] = o1;
    }
}

// ---------------- flash attention ----------------
// grid (SEQ/128, B*H), 128 threads; each thread owns one query row.
#define AQ  128     // query rows per block
#define AKV 32      // keys per tile

__global__ __launch_bounds__(128, 2)
void attn_kernel(float* __restrict__ out)
{
    __shared__ float Ks[AKV][HDIM];       // 8 KB, broadcast reads
    __shared__ float Vs[AKV][HDIM];       // 8 KB
    __shared__ float Ss[AQ][AKV + 1];     // 16.5 KB, pad -> bank (r+j)%32

    const int tid  = threadIdx.x;
    const int bh   = blockIdx.y;                  // b*NHEAD + h
    const int qrow = blockIdx.x * AQ + tid;
    const float* Qp = g_q + ((size_t)bh * SEQ + qrow) * HDIM;
    const float* Kb = g_k + (size_t)bh * SEQ * HDIM;
    const float* Vb = g_v + (size_t)bh * SEQ * HDIM;

    // q row + o accumulator fully in registers
    float4 qv[16];
    #pragma unroll
    for (int i = 0; i < 16; i++) qv[i] = *(const float4*)&Qp[i * 4];
    float4 ov[16];
    #pragma unroll
    for (int i = 0; i < 16; i++) ov[i] = make_float4(0.f, 0.f, 0.f, 0.f);

    float m = -__int_as_float(0x7f800000);  // -inf
    float l = 0.0f;

    // scores scaled so p = 2^(t - m): t = dot * (1/8) * log2(e)
    const float C = 0.125f * 1.4426950408889634f;

    #pragma unroll 1
    for (int kt = 0; kt < SEQ / AKV; kt++) {
        __syncthreads();
        // cooperative K/V tile load: 32x64 each, 4 float4 per thread per tensor
        #pragma unroll
        for (int it = 0; it < 4; it++) {
            int v   = tid + it * 128;     // 0..511 float4 slots
            int row = v >> 4;             // 16 float4 per row
            int c4  = v & 15;
            size_t g = ((size_t)kt * AKV + row) * HDIM + c4 * 4;
            *(float4*)&Ks[row][c4 * 4] = *(const float4*)&Kb[g];
            *(float4*)&Vs[row][c4 * 4] = *(const float4*)&Vb[g];
        }
        __syncthreads();

        // pass 1: scores for this thread's query row
        float mloc = m;
        #pragma unroll 4
        for (int j = 0; j < AKV; j++) {
            float s0 = 0.f, s1 = 0.f, s2 = 0.f, s3 = 0.f;
            #pragma unroll
            for (int d4 = 0; d4 < 16; d4++) {
                float4 kk = *(const float4*)&Ks[j][d4 * 4];
                s0 = fmaf(qv[d4].x, kk.x, s0);
                s1 = fmaf(qv[d4].y, kk.y, s1);
                s2 = fmaf(qv[d4].z, kk.z, s2);
                s3 = fmaf(qv[d4].w, kk.w, s3);
            }
            float t = ((s0 + s1) + (s2 + s3)) * C;
            Ss[tid][j] = t;
            mloc = fmaxf(mloc, t);
        }

        // rescale running state
        float sc = fast_exp2(m - mloc);
        m = mloc;
        l *= sc;
        #pragma unroll
        for (int i = 0; i < 16; i++) {
            ov[i].x *= sc; ov[i].y *= sc; ov[i].z *= sc; ov[i].w *= sc;
        }

        // pass 2: p = 2^(t-m); o += p * V
        #pragma unroll 4
        for (int j = 0; j < AKV; j++) {
            float pj = fast_exp2(Ss[tid][j] - m);
            l += pj;
            #pragma unroll
            for (int d4 = 0; d4 < 16; d4++) {
                float4 vv = *(const float4*)&Vs[j][d4 * 4];
                ov[d4].x = fmaf(pj, vv.x, ov[d4].x);
                ov[d4].y = fmaf(pj, vv.y, ov[d4].y);
                ov[d4].z = fmaf(pj, vv.z, ov[d4].z);
                ov[d4].w = fmaf(pj, vv.w, ov[d4].w);
            }
        }
    }

    // normalize + write out[B,S,H*Dh]
    const float inv = 1.0f / l;
    const int b = bh >> 4;
    const int h = bh & 15;
    float* op = out + ((size_t)b * SEQ + qrow) * DOUT + h * HDIM;
    #pragma unroll
    for (int i = 0; i < 16; i++) {
        float4 o = ov[i];
        o.x *= inv; o.y *= inv; o.z *= inv; o.w *= inv;
        *(float4*)&op[i * 4] = o;
    }
}

// ---------------- launch ----------------
extern "C" void kernel_launch(void* const* d_in, const int* in_sizes, int n_in,
                              void* d_out, int out_size)
{
    const float* x  = (const float*)d_in[0];
    const float* Wq = (const float*)d_in[1];
    const float* bq = (const float*)d_in[2];
    const float* Wk = (const float*)d_in[3];
    const float* bk = (const float*)d_in[4];
    const float* Wv = (const float*)d_in[5];
    const float* bv = (const float*)d_in[6];
    float* out = (float*)d_out;

    dim3 gProj(DOUT / PBN, MTOT / PBM, 3);        // (8, 64, 3)
    proj_kernel<<<gProj, 256>>>(x, Wq, bq, Wk, bk, Wv, bv);

    dim3 gAttn(SEQ / AQ, BATCH * NHEAD);          // (16, 64)
    attn_kernel<<<gAttn, 128>>>(out);
}